// round 8
// baseline (speedup 1.0000x reference)
#include <cuda_runtime.h>
#include <cstdint>

#define D 128
#define C 32
#define LSEQ 4096
#define BH 32
#define NCHUNK 128              // chunks per (b,h)
#define NC_TOTAL 4096           // total chunks
#define ASTR 36                 // 32x32 matrix row stride (pad 4, 16B-aligned rows)
#define RSTR 132                // 32x128 chunk row stride (pad 4, keeps 16B align)
#define KSTR 128                // swizzled k tile row stride (XOR swizzle, no pad)
#define VSLICE 32               // dv slice width per scan CTA
#define NSPLIT 4                // dv splits

// Scratch (allocation-free rule: __device__ globals)
__device__ float g_qn[BH * LSEQ * D];
__device__ float g_kn[BH * LSEQ * D];
__device__ float g_w [BH * LSEQ * D];
__device__ float g_u [BH * LSEQ * D];
__device__ float g_attn[NC_TOTAL * C * C];

// ---------------- packed f32x2 helpers (FFMA2 path, sm_100+) ----------------
__device__ __forceinline__ unsigned long long pk2(float v) {
    unsigned long long r;
    asm("mov.b64 %0, {%1, %1};" : "=l"(r) : "f"(v));
    return r;
}
__device__ __forceinline__ unsigned long long pkf(float lo, float hi) {
    unsigned long long r;
    asm("mov.b64 %0, {%1, %2};" : "=l"(r) : "f"(lo), "f"(hi));
    return r;
}
__device__ __forceinline__ void fma2(unsigned long long& a,
                                     unsigned long long b, unsigned long long c) {
    asm("fma.rn.f32x2 %0, %1, %2, %0;" : "+l"(a) : "l"(b), "l"(c));
}
__device__ __forceinline__ float2 up2(unsigned long long a) {
    float2 f;
    asm("mov.b64 {%0, %1}, %2;" : "=f"(f.x), "=f"(f.y) : "l"(a));
    return f;
}
__device__ __forceinline__ float hadd2(unsigned long long a) {
    float2 f = up2(a); return f.x + f.y;
}
__device__ __forceinline__ void cpa16(uint32_t s, const float* g) {
    asm volatile("cp.async.cg.shared.global [%0], [%1], 16;" :: "r"(s), "l"(g));
}

// ---------------------------------------------------------------------------
// Kernel A: per-chunk preprocessing.
// ---------------------------------------------------------------------------
__global__ void __launch_bounds__(256, 2) prep_kernel(
    const float* __restrict__ q, const float* __restrict__ k,
    const float* __restrict__ v, const float* __restrict__ beta)
{
    extern __shared__ float s[];
    float* sqn = s;                       // 32 x RSTR
    float* skn = sqn + C * RSTR;          // 32 x KSTR (XOR-swizzled chunks)
    float* skb = skn + C * KSTR;          // 32 x RSTR
    float* sv  = skb + C * RSTR;          // 32 x RSTR
    float* sA  = sv  + C * RSTR;          // 32 x ASTR

    const int nc  = blockIdx.x;
    const int t   = threadIdx.x;
    const int w   = t >> 5;
    const int lid = t & 31;
    const size_t base = (size_t)nc * (C * D);

    // ---- Phase 1: normalize + scale ----
    #pragma unroll
    for (int rr = 0; rr < 4; rr++) {
        const int r = w * 4 + rr;
        const float bet = __ldg(beta + (size_t)nc * C + r);
        float4 q4 = *(const float4*)(q + base + r * D + lid * 4);
        float4 k4 = *(const float4*)(k + base + r * D + lid * 4);
        float4 v4 = *(const float4*)(v + base + r * D + lid * 4);
        float qs = q4.x*q4.x + q4.y*q4.y + q4.z*q4.z + q4.w*q4.w;
        float ks = k4.x*k4.x + k4.y*k4.y + k4.z*k4.z + k4.w*k4.w;
        #pragma unroll
        for (int o = 16; o > 0; o >>= 1) {
            qs += __shfl_xor_sync(0xffffffffu, qs, o);
            ks += __shfl_xor_sync(0xffffffffu, ks, o);
        }
        const float qr = rsqrtf(qs + 1e-6f);
        const float kr = rsqrtf(ks + 1e-6f);
        float4 qn = make_float4(q4.x*qr, q4.y*qr, q4.z*qr, q4.w*qr);
        float4 kn = make_float4(k4.x*kr, k4.y*kr, k4.z*kr, k4.w*kr);
        float4 kb = make_float4(kn.x*bet, kn.y*bet, kn.z*bet, kn.w*bet);
        float4 vb = make_float4(v4.x*bet, v4.y*bet, v4.z*bet, v4.w*bet);
        *(float4*)(sqn + r * RSTR + lid * 4) = qn;
        // XOR-swizzled store: chunk lid of row r -> chunk lid ^ (r&7)
        *(float4*)(skn + r * KSTR + ((lid ^ (r & 7)) << 2)) = kn;
        *(float4*)(skb + r * RSTR + lid * 4) = kb;
        *(float4*)(sv  + r * RSTR + lid * 4) = vb;
        *(float4*)(g_qn + base + r * D + lid * 4) = qn;
        *(float4*)(g_kn + base + r * D + lid * 4) = kn;
    }
    __syncthreads();

    // ---- Phase 2: A (strict-lower, negated) and attn (lower incl diag) ----
    // kj read from swizzled skn (conflict-free LDS.128); row streams broadcast.
    {
        const int j  = lid;
        const int i0 = w * 4;
        const int jx = (j & 7);
        unsigned long long A0=0,A1=0,A2=0,A3=0,T0=0,T1=0,T2=0,T3=0;
        const float* kjp = skn + j * KSTR;
        const float* b0p = skb + (i0+0) * RSTR;
        const float* b1p = skb + (i0+1) * RSTR;
        const float* b2p = skb + (i0+2) * RSTR;
        const float* b3p = skb + (i0+3) * RSTR;
        const float* q0p = sqn + (i0+0) * RSTR;
        const float* q1p = sqn + (i0+1) * RSTR;
        const float* q2p = sqn + (i0+2) * RSTR;
        const float* q3p = sqn + (i0+3) * RSTR;
        #pragma unroll 4
        for (int d = 0; d < D; d += 4) {
            ulonglong2 kj = *(const ulonglong2*)(kjp + ((((d >> 2) ^ jx)) << 2));
            ulonglong2 b0 = *(const ulonglong2*)(b0p + d);
            ulonglong2 b1 = *(const ulonglong2*)(b1p + d);
            ulonglong2 b2 = *(const ulonglong2*)(b2p + d);
            ulonglong2 b3 = *(const ulonglong2*)(b3p + d);
            fma2(A0, b0.x, kj.x); fma2(A0, b0.y, kj.y);
            fma2(A1, b1.x, kj.x); fma2(A1, b1.y, kj.y);
            fma2(A2, b2.x, kj.x); fma2(A2, b2.y, kj.y);
            fma2(A3, b3.x, kj.x); fma2(A3, b3.y, kj.y);
            ulonglong2 c0 = *(const ulonglong2*)(q0p + d);
            ulonglong2 c1 = *(const ulonglong2*)(q1p + d);
            ulonglong2 c2 = *(const ulonglong2*)(q2p + d);
            ulonglong2 c3 = *(const ulonglong2*)(q3p + d);
            fma2(T0, c0.x, kj.x); fma2(T0, c0.y, kj.y);
            fma2(T1, c1.x, kj.x); fma2(T1, c1.y, kj.y);
            fma2(T2, c2.x, kj.x); fma2(T2, c2.y, kj.y);
            fma2(T3, c3.x, kj.x); fma2(T3, c3.y, kj.y);
        }
        const float a0 = hadd2(A0), a1 = hadd2(A1), a2 = hadd2(A2), a3 = hadd2(A3);
        const float t0 = hadd2(T0), t1 = hadd2(T1), t2 = hadd2(T2), t3 = hadd2(T3);
        float* ga = g_attn + (size_t)nc * (C * C);
        sA[(i0+0)*ASTR + j] = (j < i0+0) ? -a0 : 0.f;
        sA[(i0+1)*ASTR + j] = (j < i0+1) ? -a1 : 0.f;
        sA[(i0+2)*ASTR + j] = (j < i0+2) ? -a2 : 0.f;
        sA[(i0+3)*ASTR + j] = (j < i0+3) ? -a3 : 0.f;
        ga[(i0+0)*C + j] = (j <= i0+0) ? t0 : 0.f;
        ga[(i0+1)*C + j] = (j <= i0+1) ? t1 : 0.f;
        ga[(i0+2)*C + j] = (j <= i0+2) ? t2 : 0.f;
        ga[(i0+3)*C + j] = (j <= i0+3) ? t3 : 0.f;
    }
    __syncthreads();

    // ---- Phase 3: forward substitution (warp 0; lane j owns column j) ----
    if (w == 0) {
        const int j = lid;
        for (int i = 1; i < C; i++) {
            float acc = 0.f;
            for (int kk = j + 1; kk < i; kk++)
                acc += sA[i*ASTR + kk] * sA[kk*ASTR + j];
            __syncwarp();
            if (j < i) sA[i*ASTR + j] += acc;
            __syncwarp();
        }
        sA[j*ASTR + j] = 1.0f;
    }
    __syncthreads();

    // ---- Phase 4: u = inv@v , w = inv@kb (f32x2 + vectorized sA row) ----
    {
        const int i  = t >> 3;
        const int dl = (t & 7) * 4;
        #pragma unroll
        for (int db = 0; db < 4; db++) {
            const int d = db * 32 + dl;
            unsigned long long au01=0, au23=0, aw01=0, aw23=0;
            #pragma unroll 4
            for (int j0 = 0; j0 < C; j0 += 4) {
                float4 a4 = *(const float4*)(sA + i*ASTR + j0);
                #pragma unroll
                for (int jj = 0; jj < 4; jj++) {
                    const float av = (&a4.x)[jj];
                    unsigned long long a2 = pk2(av);
                    ulonglong2 v2 = *(const ulonglong2*)(sv  + (j0+jj)*RSTR + d);
                    ulonglong2 b2 = *(const ulonglong2*)(skb + (j0+jj)*RSTR + d);
                    fma2(au01, a2, v2.x); fma2(au23, a2, v2.y);
                    fma2(aw01, a2, b2.x); fma2(aw23, a2, b2.y);
                }
            }
            float2 l, h;
            l = up2(au01); h = up2(au23);
            *(float4*)(g_u + base + i*D + d) = make_float4(l.x, l.y, h.x, h.y);
            l = up2(aw01); h = up2(aw23);
            *(float4*)(g_w + base + i*D + d) = make_float4(l.x, l.y, h.x, h.y);
        }
    }
}

// ---------------------------------------------------------------------------
// Scan kernel: 512 threads. Sequential over chunks, parallel over (b,h) x dv.
// Double-buffered cp.async prefetch. Phase3 (out) and phase4 (S update) run
// concurrently on disjoint thread halves.
// ---------------------------------------------------------------------------
#define SBUF (3 * C * RSTR + 2 * C * ASTR)   // q,k,w tiles + u0 + attn per buffer

__device__ __forceinline__ void prefetch_chunk(
    uint32_t smb, int ci, int t, int v0,
    const float* gq, const float* gk, const float* gw,
    const float* gu, const float* ga)
{
    const int w   = t >> 5;
    const int lid = t & 31;
    const size_t cb = (size_t)ci * (C * D);
    const uint32_t OK  = (uint32_t)(C * RSTR) * 4u;
    const uint32_t OW  = 2u * OK;
    const uint32_t OU0 = 3u * OK;
    const uint32_t OAT = OU0 + (uint32_t)(C * ASTR) * 4u;
    #pragma unroll
    for (int rr = 0; rr < 2; rr++) {
        const int r = w * 2 + rr;
        const uint32_t off = (uint32_t)(r * RSTR + lid * 4) * 4u;
        cpa16(smb +      off, gq + cb + r * D + lid * 4);
        cpa16(smb + OK + off, gk + cb + r * D + lid * 4);
        cpa16(smb + OW + off, gw + cb + r * D + lid * 4);
    }
    if (t < 256) {
        const int c  = t >> 3;
        const int v4 = (t & 7) * 4;
        cpa16(smb + OU0 + (uint32_t)(c * ASTR + v4) * 4u, gu + cb + c * D + v0 + v4);
        cpa16(smb + OAT + (uint32_t)(c * ASTR + v4) * 4u,
              ga + (size_t)ci * (C * C) + c * C + v4);
    }
    asm volatile("cp.async.commit_group;");
}

__global__ void __launch_bounds__(512, 1) scan_kernel(float* __restrict__ out)
{
    extern __shared__ float s[];
    float* sS  = s;                         // 128 x VSLICE
    float* sb0 = sS + D * VSLICE;
    float* sb1 = sb0 + SBUF;
    float* sui = sb1 + SBUF;                // 32 x ASTR
    float* sPU = sui + C * ASTR;            // 32 x ASTR (dh1 partial of w@S)
    float* sPQ = sPU + C * ASTR;            // 32 x ASTR (partial then total q@S)

    const int bh  = blockIdx.y;
    const int v0  = blockIdx.x * VSLICE;
    const int t   = threadIdx.x;
    // phase-2 mapping: 1 c-row per thread, d split across halves of CTA
    const int dh  = t >> 8;                 // 0/1 -> d in [0,64) / [64,128)
    const int r2  = (t >> 3) & 31;          // c row
    const int v4  = (t & 7) * 4;
    // phase-4 mapping (threads 0..255)
    const int r4  = t >> 3;

    // zero S
    #pragma unroll
    for (int rr = 0; rr < 2; rr++)
        *(float4*)(sS + (rr * 512 + t) * 4) = make_float4(0.f, 0.f, 0.f, 0.f);

    const uint32_t smb0 = (uint32_t)__cvta_generic_to_shared(sb0);
    const uint32_t smb1 = (uint32_t)__cvta_generic_to_shared(sb1);

    const size_t bhb = (size_t)bh * LSEQ * D;
    const float* gq = g_qn + bhb;
    const float* gk = g_kn + bhb;
    const float* gw = g_w  + bhb;
    const float* gu = g_u  + bhb;
    const float* ga = g_attn + (size_t)bh * NCHUNK * (C * C);

    prefetch_chunk(smb0, 0, t, v0, gq, gk, gw, gu, ga);

    for (int ci = 0; ci < NCHUNK; ci++) {
        float* B = (ci & 1) ? sb1 : sb0;
        const uint32_t smn = (ci & 1) ? smb0 : smb1;
        const float* sq  = B;
        const float* sk  = B + C * RSTR;
        const float* sw  = B + 2 * C * RSTR;
        const float* su0 = B + 3 * C * RSTR;
        const float* sat = su0 + C * ASTR;

        asm volatile("cp.async.wait_group 0;");
        __syncthreads();                        // tiles ready + prev S update done

        const int cn = (ci + 1 < NCHUNK) ? ci + 1 : ci;
        prefetch_chunk(smn, cn, t, v0, gq, gk, gw, gu, ga);

        // ---- phase 2: half-d GEMV, 1 row/thread, float4 weight broadcasts ----
        unsigned long long aUx=0, aUy=0, aQx=0, aQy=0;
        {
            const int dbeg = dh * 64;
            const float* wp = sw + r2 * RSTR + dbeg;
            const float* qp = sq + r2 * RSTR + dbeg;
            const float* Sp = sS + dbeg * VSLICE + v4;
            #pragma unroll 4
            for (int d4 = 0; d4 < 64; d4 += 4) {
                float4 wv = *(const float4*)(wp + d4);
                float4 qv = *(const float4*)(qp + d4);
                #pragma unroll
                for (int i = 0; i < 4; i++) {
                    ulonglong2 S2 = *(const ulonglong2*)(Sp + (d4 + i) * VSLICE);
                    unsigned long long w2 = pk2((&wv.x)[i]);
                    unsigned long long q2 = pk2((&qv.x)[i]);
                    fma2(aUx, w2, S2.x); fma2(aUy, w2, S2.y);
                    fma2(aQx, q2, S2.x); fma2(aQy, q2, S2.y);
                }
            }
        }
        if (dh) {                               // store d-high partials
            float2 l, h;
            l = up2(aUx); h = up2(aUy);
            *(float4*)(sPU + r2 * ASTR + v4) = make_float4(l.x, l.y, h.x, h.y);
            l = up2(aQx); h = up2(aQy);
            *(float4*)(sPQ + r2 * ASTR + v4) = make_float4(l.x, l.y, h.x, h.y);
        }
        __syncthreads();
        if (!dh) {                              // combine halves, u_i, total q@S
            float4 pU = *(float4*)(sPU + r2 * ASTR + v4);
            float4 pQ = *(float4*)(sPQ + r2 * ASTR + v4);
            float4 u0 = *(const float4*)(su0 + r2 * ASTR + v4);
            float2 l, h;
            l = up2(aUx); h = up2(aUy);
            *(float4*)(sui + r2 * ASTR + v4) = make_float4(
                u0.x - (l.x + pU.x), u0.y - (l.y + pU.y),
                u0.z - (h.x + pU.z), u0.w - (h.y + pU.w));
            l = up2(aQx); h = up2(aQy);
            *(float4*)(sPQ + r2 * ASTR + v4) = make_float4(
                l.x + pQ.x, l.y + pQ.y, h.x + pQ.z, h.y + pQ.w);
        }
        __syncthreads();

        if (dh) {
            // ---- phase 3 (threads 256..511): out = q@S + attn @ u_i ----
            float4 a0 = *(const float4*)(sPQ + r2 * ASTR + v4);
            unsigned long long o01 = pkf(a0.x, a0.y);
            unsigned long long o23 = pkf(a0.z, a0.w);
            #pragma unroll 8
            for (int e = 0; e < C; e++) {
                unsigned long long a2 = pk2(sat[r2 * ASTR + e]);
                ulonglong2 u2 = *(const ulonglong2*)(sui + e * ASTR + v4);
                fma2(o01, a2, u2.x); fma2(o23, a2, u2.y);
            }
            float2 l = up2(o01), h = up2(o23);
            *(float4*)(out + bhb + (size_t)ci * (C * D) + r2 * D + v0 + v4) =
                make_float4(l.x, l.y, h.x, h.y);
        } else {
            // ---- phase 4 (threads 0..255): S[d,v] += sum_e k[e,d]*u_i[e,v] ----
            unsigned long long A0=0,A1=0,A2=0,A3=0,A4=0,A5=0,A6=0,A7=0;
            #pragma unroll 4
            for (int e = 0; e < C; e++) {
                ulonglong2 u2 = *(const ulonglong2*)(sui + e * ASTR + v4);
                unsigned long long k0 = pk2(sk[e * RSTR + r4]);
                unsigned long long k1 = pk2(sk[e * RSTR + r4 + 32]);
                unsigned long long k2 = pk2(sk[e * RSTR + r4 + 64]);
                unsigned long long k3 = pk2(sk[e * RSTR + r4 + 96]);
                fma2(A0, k0, u2.x); fma2(A1, k0, u2.y);
                fma2(A2, k1, u2.x); fma2(A3, k1, u2.y);
                fma2(A4, k2, u2.x); fma2(A5, k2, u2.y);
                fma2(A6, k3, u2.x); fma2(A7, k3, u2.y);
            }
            float2 l, h;
            float4* p0 = (float4*)(sS + (r4      ) * VSLICE + v4);
            float4* p1 = (float4*)(sS + (r4 +  32) * VSLICE + v4);
            float4* p2 = (float4*)(sS + (r4 +  64) * VSLICE + v4);
            float4* p3 = (float4*)(sS + (r4 +  96) * VSLICE + v4);
            float4 t0 = *p0, t1 = *p1, t2 = *p2, t3 = *p3;
            l = up2(A0); h = up2(A1);
            t0.x += l.x; t0.y += l.y; t0.z += h.x; t0.w += h.y;
            l = up2(A2); h = up2(A3);
            t1.x += l.x; t1.y += l.y; t1.z += h.x; t1.w += h.y;
            l = up2(A4); h = up2(A5);
            t2.x += l.x; t2.y += l.y; t2.z += h.x; t2.w += h.y;
            l = up2(A6); h = up2(A7);
            t3.x += l.x; t3.y += l.y; t3.z += h.x; t3.w += h.y;
            *p0 = t0; *p1 = t1; *p2 = t2; *p3 = t3;
        }
    }
}

// ---------------------------------------------------------------------------
extern "C" void kernel_launch(void* const* d_in, const int* in_sizes, int n_in,
                              void* d_out, int out_size)
{
    const float* q    = (const float*)d_in[0];
    const float* k    = (const float*)d_in[1];
    const float* v    = (const float*)d_in[2];
    const float* beta = (const float*)d_in[3];
    float* out = (float*)d_out;

    const size_t smemA = (size_t)(3 * C * RSTR + C * KSTR + C * ASTR) * sizeof(float);
    const size_t smemB = (size_t)(D * VSLICE + 2 * SBUF + 3 * C * ASTR)
                         * sizeof(float);

    cudaFuncSetAttribute(prep_kernel, cudaFuncAttributeMaxDynamicSharedMemorySize,
                         (int)smemA);
    cudaFuncSetAttribute(scan_kernel, cudaFuncAttributeMaxDynamicSharedMemorySize,
                         (int)smemB);

    prep_kernel<<<NC_TOTAL, 256, smemA>>>(q, k, v, beta);
    scan_kernel<<<dim3(NSPLIT, BH), 512, smemB>>>(out);
}

// round 10
// speedup vs baseline: 1.1355x; 1.1355x over previous
#include <cuda_runtime.h>
#include <cstdint>

#define D 128
#define C 32
#define LSEQ 4096
#define BH 32
#define NCHUNK 128              // chunks per (b,h)
#define NC_TOTAL 4096           // total chunks
#define ASTR 36                 // 32x32 matrix row stride (pad 4, 16B-aligned rows)
#define RSTR 132                // 32x128 chunk row stride (pad 4, keeps 16B align)
#define KSTR 128                // swizzled k tile row stride (XOR swizzle, no pad)
#define VSLICE 32               // dv slice width per scan CTA
#define NSPLIT 4                // dv splits

// Scratch (allocation-free rule: __device__ globals)
__device__ float g_qn[BH * LSEQ * D];
__device__ float g_kn[BH * LSEQ * D];
__device__ float g_w [BH * LSEQ * D];
__device__ float g_u [BH * LSEQ * D];
__device__ float g_attn[NC_TOTAL * C * C];

// ---------------- packed f32x2 helpers (FFMA2 path, sm_100+) ----------------
__device__ __forceinline__ unsigned long long pk2(float v) {
    unsigned long long r;
    asm("mov.b64 %0, {%1, %1};" : "=l"(r) : "f"(v));
    return r;
}
__device__ __forceinline__ unsigned long long pkf(float lo, float hi) {
    unsigned long long r;
    asm("mov.b64 %0, {%1, %2};" : "=l"(r) : "f"(lo), "f"(hi));
    return r;
}
__device__ __forceinline__ void fma2(unsigned long long& a,
                                     unsigned long long b, unsigned long long c) {
    asm("fma.rn.f32x2 %0, %1, %2, %0;" : "+l"(a) : "l"(b), "l"(c));
}
__device__ __forceinline__ float2 up2(unsigned long long a) {
    float2 f;
    asm("mov.b64 {%0, %1}, %2;" : "=f"(f.x), "=f"(f.y) : "l"(a));
    return f;
}
__device__ __forceinline__ float hadd2(unsigned long long a) {
    float2 f = up2(a); return f.x + f.y;
}
__device__ __forceinline__ void cpa16(uint32_t s, const float* g) {
    asm volatile("cp.async.cg.shared.global [%0], [%1], 16;" :: "r"(s), "l"(g));
}

// ---------------------------------------------------------------------------
// Kernel A: per-chunk preprocessing. (unchanged)
// ---------------------------------------------------------------------------
__global__ void __launch_bounds__(256, 2) prep_kernel(
    const float* __restrict__ q, const float* __restrict__ k,
    const float* __restrict__ v, const float* __restrict__ beta)
{
    extern __shared__ float s[];
    float* sqn = s;                       // 32 x RSTR
    float* skn = sqn + C * RSTR;          // 32 x KSTR (XOR-swizzled chunks)
    float* skb = skn + C * KSTR;          // 32 x RSTR
    float* sv  = skb + C * RSTR;          // 32 x RSTR
    float* sA  = sv  + C * RSTR;          // 32 x ASTR

    const int nc  = blockIdx.x;
    const int t   = threadIdx.x;
    const int w   = t >> 5;
    const int lid = t & 31;
    const size_t base = (size_t)nc * (C * D);

    // ---- Phase 1: normalize + scale ----
    #pragma unroll
    for (int rr = 0; rr < 4; rr++) {
        const int r = w * 4 + rr;
        const float bet = __ldg(beta + (size_t)nc * C + r);
        float4 q4 = *(const float4*)(q + base + r * D + lid * 4);
        float4 k4 = *(const float4*)(k + base + r * D + lid * 4);
        float4 v4 = *(const float4*)(v + base + r * D + lid * 4);
        float qs = q4.x*q4.x + q4.y*q4.y + q4.z*q4.z + q4.w*q4.w;
        float ks = k4.x*k4.x + k4.y*k4.y + k4.z*k4.z + k4.w*k4.w;
        #pragma unroll
        for (int o = 16; o > 0; o >>= 1) {
            qs += __shfl_xor_sync(0xffffffffu, qs, o);
            ks += __shfl_xor_sync(0xffffffffu, ks, o);
        }
        const float qr = rsqrtf(qs + 1e-6f);
        const float kr = rsqrtf(ks + 1e-6f);
        float4 qn = make_float4(q4.x*qr, q4.y*qr, q4.z*qr, q4.w*qr);
        float4 kn = make_float4(k4.x*kr, k4.y*kr, k4.z*kr, k4.w*kr);
        float4 kb = make_float4(kn.x*bet, kn.y*bet, kn.z*bet, kn.w*bet);
        float4 vb = make_float4(v4.x*bet, v4.y*bet, v4.z*bet, v4.w*bet);
        *(float4*)(sqn + r * RSTR + lid * 4) = qn;
        *(float4*)(skn + r * KSTR + ((lid ^ (r & 7)) << 2)) = kn;
        *(float4*)(skb + r * RSTR + lid * 4) = kb;
        *(float4*)(sv  + r * RSTR + lid * 4) = vb;
        *(float4*)(g_qn + base + r * D + lid * 4) = qn;
        *(float4*)(g_kn + base + r * D + lid * 4) = kn;
    }
    __syncthreads();

    // ---- Phase 2: A (strict-lower, negated) and attn (lower incl diag) ----
    {
        const int j  = lid;
        const int i0 = w * 4;
        const int jx = (j & 7);
        unsigned long long A0=0,A1=0,A2=0,A3=0,T0=0,T1=0,T2=0,T3=0;
        const float* kjp = skn + j * KSTR;
        const float* b0p = skb + (i0+0) * RSTR;
        const float* b1p = skb + (i0+1) * RSTR;
        const float* b2p = skb + (i0+2) * RSTR;
        const float* b3p = skb + (i0+3) * RSTR;
        const float* q0p = sqn + (i0+0) * RSTR;
        const float* q1p = sqn + (i0+1) * RSTR;
        const float* q2p = sqn + (i0+2) * RSTR;
        const float* q3p = sqn + (i0+3) * RSTR;
        #pragma unroll 4
        for (int d = 0; d < D; d += 4) {
            ulonglong2 kj = *(const ulonglong2*)(kjp + ((((d >> 2) ^ jx)) << 2));
            ulonglong2 b0 = *(const ulonglong2*)(b0p + d);
            ulonglong2 b1 = *(const ulonglong2*)(b1p + d);
            ulonglong2 b2 = *(const ulonglong2*)(b2p + d);
            ulonglong2 b3 = *(const ulonglong2*)(b3p + d);
            fma2(A0, b0.x, kj.x); fma2(A0, b0.y, kj.y);
            fma2(A1, b1.x, kj.x); fma2(A1, b1.y, kj.y);
            fma2(A2, b2.x, kj.x); fma2(A2, b2.y, kj.y);
            fma2(A3, b3.x, kj.x); fma2(A3, b3.y, kj.y);
            ulonglong2 c0 = *(const ulonglong2*)(q0p + d);
            ulonglong2 c1 = *(const ulonglong2*)(q1p + d);
            ulonglong2 c2 = *(const ulonglong2*)(q2p + d);
            ulonglong2 c3 = *(const ulonglong2*)(q3p + d);
            fma2(T0, c0.x, kj.x); fma2(T0, c0.y, kj.y);
            fma2(T1, c1.x, kj.x); fma2(T1, c1.y, kj.y);
            fma2(T2, c2.x, kj.x); fma2(T2, c2.y, kj.y);
            fma2(T3, c3.x, kj.x); fma2(T3, c3.y, kj.y);
        }
        const float a0 = hadd2(A0), a1 = hadd2(A1), a2 = hadd2(A2), a3 = hadd2(A3);
        const float t0 = hadd2(T0), t1 = hadd2(T1), t2 = hadd2(T2), t3 = hadd2(T3);
        float* ga = g_attn + (size_t)nc * (C * C);
        sA[(i0+0)*ASTR + j] = (j < i0+0) ? -a0 : 0.f;
        sA[(i0+1)*ASTR + j] = (j < i0+1) ? -a1 : 0.f;
        sA[(i0+2)*ASTR + j] = (j < i0+2) ? -a2 : 0.f;
        sA[(i0+3)*ASTR + j] = (j < i0+3) ? -a3 : 0.f;
        ga[(i0+0)*C + j] = (j <= i0+0) ? t0 : 0.f;
        ga[(i0+1)*C + j] = (j <= i0+1) ? t1 : 0.f;
        ga[(i0+2)*C + j] = (j <= i0+2) ? t2 : 0.f;
        ga[(i0+3)*C + j] = (j <= i0+3) ? t3 : 0.f;
    }
    __syncthreads();

    // ---- Phase 3: forward substitution (warp 0; lane j owns column j) ----
    if (w == 0) {
        const int j = lid;
        for (int i = 1; i < C; i++) {
            float acc = 0.f;
            for (int kk = j + 1; kk < i; kk++)
                acc += sA[i*ASTR + kk] * sA[kk*ASTR + j];
            __syncwarp();
            if (j < i) sA[i*ASTR + j] += acc;
            __syncwarp();
        }
        sA[j*ASTR + j] = 1.0f;
    }
    __syncthreads();

    // ---- Phase 4: u = inv@v , w = inv@kb ----
    {
        const int i  = t >> 3;
        const int dl = (t & 7) * 4;
        #pragma unroll
        for (int db = 0; db < 4; db++) {
            const int d = db * 32 + dl;
            unsigned long long au01=0, au23=0, aw01=0, aw23=0;
            #pragma unroll 4
            for (int j0 = 0; j0 < C; j0 += 4) {
                float4 a4 = *(const float4*)(sA + i*ASTR + j0);
                #pragma unroll
                for (int jj = 0; jj < 4; jj++) {
                    const float av = (&a4.x)[jj];
                    unsigned long long a2 = pk2(av);
                    ulonglong2 v2 = *(const ulonglong2*)(sv  + (j0+jj)*RSTR + d);
                    ulonglong2 b2 = *(const ulonglong2*)(skb + (j0+jj)*RSTR + d);
                    fma2(au01, a2, v2.x); fma2(au23, a2, v2.y);
                    fma2(aw01, a2, b2.x); fma2(aw23, a2, b2.y);
                }
            }
            float2 l, h;
            l = up2(au01); h = up2(au23);
            *(float4*)(g_u + base + i*D + d) = make_float4(l.x, l.y, h.x, h.y);
            l = up2(aw01); h = up2(aw23);
            *(float4*)(g_w + base + i*D + d) = make_float4(l.x, l.y, h.x, h.y);
        }
    }
}

// ---------------------------------------------------------------------------
// Scan kernel: 256 threads. Phase 2 uses 4-row register tiling + d-quarters:
// each S LDS.128 feeds 4 output rows of BOTH w@S and q@S (S traffic halved
// vs R7). Quarter partials combined through smem.
// ---------------------------------------------------------------------------
#define SBUF (3 * C * RSTR + 2 * C * ASTR)   // q,k,w tiles + u0 + attn per buffer
#define PMAT (C * ASTR)                       // one 32x32 partial matrix

__device__ __forceinline__ void prefetch_chunk(
    uint32_t smb, int ci, int w, int lid, int c, int v4, int v0,
    const float* gq, const float* gk, const float* gw,
    const float* gu, const float* ga)
{
    const size_t cb = (size_t)ci * (C * D);
    const uint32_t OK  = (uint32_t)(C * RSTR) * 4u;
    const uint32_t OW  = 2u * OK;
    const uint32_t OU0 = 3u * OK;
    const uint32_t OAT = OU0 + (uint32_t)(C * ASTR) * 4u;
    #pragma unroll
    for (int rr = 0; rr < 4; rr++) {
        const int r = w * 4 + rr;
        const uint32_t off = (uint32_t)(r * RSTR + lid * 4) * 4u;
        cpa16(smb +      off, gq + cb + r * D + lid * 4);
        cpa16(smb + OK + off, gk + cb + r * D + lid * 4);
        cpa16(smb + OW + off, gw + cb + r * D + lid * 4);
    }
    cpa16(smb + OU0 + (uint32_t)(c * ASTR + v4) * 4u, gu + cb + c * D + v0 + v4);
    cpa16(smb + OAT + (uint32_t)(c * ASTR + v4) * 4u,
          ga + (size_t)ci * (C * C) + c * C + v4);
    asm volatile("cp.async.commit_group;");
}

__global__ void __launch_bounds__(256, 1) scan_kernel(float* __restrict__ out)
{
    extern __shared__ float s[];
    float* sS  = s;                         // 128 x VSLICE
    float* sb0 = sS + D * VSLICE;
    float* sb1 = sb0 + SBUF;
    float* sui = sb1 + SBUF;                // 32 x ASTR
    float* sPQ = sui + C * ASTR;            // 32 x ASTR (final q@S)
    float* sPP = sPQ + C * ASTR;            // 6 x PMAT partial matrices

    const int bh  = blockIdx.y;
    const int v0  = blockIdx.x * VSLICE;
    const int t   = threadIdx.x;
    const int w   = t >> 5;
    const int lid = t & 31;
    // phase-2 mapping: v4-group x 4-row block x d-quarter
    const int v4  = (t & 7) * 4;
    const int r0  = ((t >> 3) & 7) * 4;     // rows r0..r0+3
    const int dq  = t >> 6;                 // d quarter 0..3
    // phase-3/4 mapping
    const int c   = t >> 3;

    // zero S
    #pragma unroll
    for (int rr = 0; rr < 4; rr++)
        *(float4*)(sS + (rr * 256 + t) * 4) = make_float4(0.f, 0.f, 0.f, 0.f);

    const uint32_t smb0 = (uint32_t)__cvta_generic_to_shared(sb0);
    const uint32_t smb1 = (uint32_t)__cvta_generic_to_shared(sb1);

    const size_t bhb = (size_t)bh * LSEQ * D;
    const float* gq = g_qn + bhb;
    const float* gk = g_kn + bhb;
    const float* gw = g_w  + bhb;
    const float* gu = g_u  + bhb;
    const float* ga = g_attn + (size_t)bh * NCHUNK * (C * C);

    prefetch_chunk(smb0, 0, w, lid, c, v4, v0, gq, gk, gw, gu, ga);

    for (int ci = 0; ci < NCHUNK; ci++) {
        float* B = (ci & 1) ? sb1 : sb0;
        const uint32_t smn = (ci & 1) ? smb0 : smb1;
        const float* sq  = B;
        const float* sk  = B + C * RSTR;
        const float* sw  = B + 2 * C * RSTR;
        const float* su0 = B + 3 * C * RSTR;
        const float* sat = su0 + C * ASTR;

        asm volatile("cp.async.wait_group 0;");
        __syncthreads();                    // tiles ready + prev S update done

        const int cn = (ci + 1 < NCHUNK) ? ci + 1 : ci;
        prefetch_chunk(smn, cn, w, lid, c, v4, v0, gq, gk, gw, gu, ga);

        // ---- phase 2: quarter-d GEMV, 4 rows/thread ----
        unsigned long long aU[4][2], aQ[4][2];
        #pragma unroll
        for (int r = 0; r < 4; r++) {
            aU[r][0]=0; aU[r][1]=0; aQ[r][0]=0; aQ[r][1]=0;
        }
        {
            const int dbeg = dq * 32;
            const float* wp = sw + dbeg;
            const float* qp = sq + dbeg;
            const float* Sp = sS + dbeg * VSLICE + v4;
            #pragma unroll 2
            for (int dg = 0; dg < 32; dg += 4) {
                float4 wv[4], qv[4];
                #pragma unroll
                for (int r = 0; r < 4; r++) {
                    wv[r] = *(const float4*)(wp + (r0 + r) * RSTR + dg);
                    qv[r] = *(const float4*)(qp + (r0 + r) * RSTR + dg);
                }
                #pragma unroll
                for (int i = 0; i < 4; i++) {
                    ulonglong2 S2 = *(const ulonglong2*)(Sp + (dg + i) * VSLICE);
                    #pragma unroll
                    for (int r = 0; r < 4; r++) {
                        unsigned long long w2 = pk2((&wv[r].x)[i]);
                        unsigned long long q2 = pk2((&qv[r].x)[i]);
                        fma2(aU[r][0], w2, S2.x); fma2(aU[r][1], w2, S2.y);
                        fma2(aQ[r][0], q2, S2.x); fma2(aQ[r][1], q2, S2.y);
                    }
                }
            }
        }
        if (dq) {                           // quarters 1..3 store partials
            float* PU = sPP + (dq - 1) * PMAT;
            float* PQ = sPP + (2 + dq) * PMAT;
            #pragma unroll
            for (int r = 0; r < 4; r++) {
                float2 l, h;
                l = up2(aU[r][0]); h = up2(aU[r][1]);
                *(float4*)(PU + (r0 + r) * ASTR + v4) = make_float4(l.x, l.y, h.x, h.y);
                l = up2(aQ[r][0]); h = up2(aQ[r][1]);
                *(float4*)(PQ + (r0 + r) * ASTR + v4) = make_float4(l.x, l.y, h.x, h.y);
            }
        }
        __syncthreads();
        if (!dq) {                          // quarter 0 combines; u_i and q@S
            #pragma unroll
            for (int r = 0; r < 4; r++) {
                const int row = r0 + r;
                float4 u0 = *(const float4*)(su0 + row * ASTR + v4);
                float2 l, h;
                l = up2(aU[r][0]); h = up2(aU[r][1]);
                float4 su = make_float4(l.x, l.y, h.x, h.y);
                l = up2(aQ[r][0]); h = up2(aQ[r][1]);
                float4 sqv = make_float4(l.x, l.y, h.x, h.y);
                #pragma unroll
                for (int p = 0; p < 3; p++) {
                    float4 pu = *(const float4*)(sPP + p * PMAT + row * ASTR + v4);
                    float4 pq = *(const float4*)(sPP + (3 + p) * PMAT + row * ASTR + v4);
                    su.x += pu.x; su.y += pu.y; su.z += pu.z; su.w += pu.w;
                    sqv.x += pq.x; sqv.y += pq.y; sqv.z += pq.z; sqv.w += pq.w;
                }
                *(float4*)(sui + row * ASTR + v4) = make_float4(
                    u0.x - su.x, u0.y - su.y, u0.z - su.z, u0.w - su.w);
                *(float4*)(sPQ + row * ASTR + v4) = sqv;
            }
        }
        __syncthreads();

        // ---- phase 3: out = q@S + attn @ u_i (all 256 threads) ----
        {
            float4 a0 = *(const float4*)(sPQ + c * ASTR + v4);
            unsigned long long o01 = pkf(a0.x, a0.y);
            unsigned long long o23 = pkf(a0.z, a0.w);
            #pragma unroll 8
            for (int e = 0; e < C; e++) {
                unsigned long long a2 = pk2(sat[c * ASTR + e]);
                ulonglong2 u2 = *(const ulonglong2*)(sui + e * ASTR + v4);
                fma2(o01, a2, u2.x); fma2(o23, a2, u2.y);
            }
            float2 l = up2(o01), h = up2(o23);
            *(float4*)(out + bhb + (size_t)ci * (C * D) + c * D + v0 + v4) =
                make_float4(l.x, l.y, h.x, h.y);
        }

        // ---- phase 4: S[d,v] += sum_e k[e,d] * u_i[e,v] ----
        {
            unsigned long long A0=0,A1=0,A2=0,A3=0,A4=0,A5=0,A6=0,A7=0;
            #pragma unroll 4
            for (int e = 0; e < C; e++) {
                ulonglong2 u2 = *(const ulonglong2*)(sui + e * ASTR + v4);
                unsigned long long k0 = pk2(sk[e * RSTR + c]);
                unsigned long long k1 = pk2(sk[e * RSTR + c + 32]);
                unsigned long long k2 = pk2(sk[e * RSTR + c + 64]);
                unsigned long long k3 = pk2(sk[e * RSTR + c + 96]);
                fma2(A0, k0, u2.x); fma2(A1, k0, u2.y);
                fma2(A2, k1, u2.x); fma2(A3, k1, u2.y);
                fma2(A4, k2, u2.x); fma2(A5, k2, u2.y);
                fma2(A6, k3, u2.x); fma2(A7, k3, u2.y);
            }
            float2 l, h;
            float4* p0 = (float4*)(sS + (c      ) * VSLICE + v4);
            float4* p1 = (float4*)(sS + (c +  32) * VSLICE + v4);
            float4* p2 = (float4*)(sS + (c +  64) * VSLICE + v4);
            float4* p3 = (float4*)(sS + (c +  96) * VSLICE + v4);
            float4 t0 = *p0, t1 = *p1, t2 = *p2, t3 = *p3;
            l = up2(A0); h = up2(A1);
            t0.x += l.x; t0.y += l.y; t0.z += h.x; t0.w += h.y;
            l = up2(A2); h = up2(A3);
            t1.x += l.x; t1.y += l.y; t1.z += h.x; t1.w += h.y;
            l = up2(A4); h = up2(A5);
            t2.x += l.x; t2.y += l.y; t2.z += h.x; t2.w += h.y;
            l = up2(A6); h = up2(A7);
            t3.x += l.x; t3.y += l.y; t3.z += h.x; t3.w += h.y;
            *p0 = t0; *p1 = t1; *p2 = t2; *p3 = t3;
        }
    }
}

// ---------------------------------------------------------------------------
extern "C" void kernel_launch(void* const* d_in, const int* in_sizes, int n_in,
                              void* d_out, int out_size)
{
    const float* q    = (const float*)d_in[0];
    const float* k    = (const float*)d_in[1];
    const float* v    = (const float*)d_in[2];
    const float* beta = (const float*)d_in[3];
    float* out = (float*)d_out;

    const size_t smemA = (size_t)(3 * C * RSTR + C * KSTR + C * ASTR) * sizeof(float);
    const size_t smemB = (size_t)(D * VSLICE + 2 * SBUF + 2 * C * ASTR + 6 * PMAT)
                         * sizeof(float);

    cudaFuncSetAttribute(prep_kernel, cudaFuncAttributeMaxDynamicSharedMemorySize,
                         (int)smemA);
    cudaFuncSetAttribute(scan_kernel, cudaFuncAttributeMaxDynamicSharedMemorySize,
                         (int)smemB);

    prep_kernel<<<NC_TOTAL, 256, smemA>>>(q, k, v, beta);
    scan_kernel<<<dim3(NSPLIT, BH), 256, smemB>>>(out);
}

// round 11
// speedup vs baseline: 1.2560x; 1.1060x over previous
#include <cuda_runtime.h>
#include <cstdint>

#define D 128
#define C 32
#define LSEQ 4096
#define BH 32
#define NCHUNK 128              // chunks per (b,h)
#define NC_TOTAL 4096           // total chunks
#define ASTR 36                 // 32x32 matrix row stride (pad 4, 16B-aligned rows)
#define RSTR 132                // 32x128 chunk row stride (pad 4, keeps 16B align)
#define KSTR 128                // swizzled k tile row stride (XOR swizzle, no pad)
#define VSLICE 32               // dv slice width per scan CTA
#define NSPLIT 4                // dv splits

// Scratch (allocation-free rule: __device__ globals)
__device__ float g_qn[BH * LSEQ * D];
__device__ float g_kn[BH * LSEQ * D];
__device__ float g_w [BH * LSEQ * D];
__device__ float g_u [BH * LSEQ * D];
__device__ float g_attn[NC_TOTAL * C * C];

// ---------------- packed f32x2 helpers (FFMA2 path, sm_100+) ----------------
__device__ __forceinline__ unsigned long long pk2(float v) {
    unsigned long long r;
    asm("mov.b64 %0, {%1, %1};" : "=l"(r) : "f"(v));
    return r;
}
__device__ __forceinline__ unsigned long long pkf(float lo, float hi) {
    unsigned long long r;
    asm("mov.b64 %0, {%1, %2};" : "=l"(r) : "f"(lo), "f"(hi));
    return r;
}
__device__ __forceinline__ void fma2(unsigned long long& a,
                                     unsigned long long b, unsigned long long c) {
    asm("fma.rn.f32x2 %0, %1, %2, %0;" : "+l"(a) : "l"(b), "l"(c));
}
__device__ __forceinline__ float2 up2(unsigned long long a) {
    float2 f;
    asm("mov.b64 {%0, %1}, %2;" : "=f"(f.x), "=f"(f.y) : "l"(a));
    return f;
}
__device__ __forceinline__ float hadd2(unsigned long long a) {
    float2 f = up2(a); return f.x + f.y;
}
__device__ __forceinline__ void cpa16(uint32_t s, const float* g) {
    asm volatile("cp.async.cg.shared.global [%0], [%1], 16;" :: "r"(s), "l"(g));
}

// ---------------------------------------------------------------------------
// Kernel A: per-chunk preprocessing.
// Phase 3 redesigned: blocked unit-lower-triangular inverse.
//   inv(I - A) = [[X11, 0], [X22*A21*X11, X22]]
// with X11, X22 = 16x16 substitutions running concurrently on warps 0 and 1,
// and the Schur combine as two 16^3 matmuls over all 256 threads.
// ---------------------------------------------------------------------------
__global__ void __launch_bounds__(256, 2) prep_kernel(
    const float* __restrict__ q, const float* __restrict__ k,
    const float* __restrict__ v, const float* __restrict__ beta)
{
    extern __shared__ float s[];
    float* sqn = s;                       // 32 x RSTR
    float* skn = sqn + C * RSTR;          // 32 x KSTR (XOR-swizzled chunks)
    float* skb = skn + C * KSTR;          // 32 x RSTR
    float* sv  = skb + C * RSTR;          // 32 x RSTR
    float* sA  = sv  + C * RSTR;          // 32 x ASTR
    float* sP  = sA  + C * ASTR;          // 16 x 17 Schur temp

    const int nc  = blockIdx.x;
    const int t   = threadIdx.x;
    const int w   = t >> 5;
    const int lid = t & 31;
    const size_t base = (size_t)nc * (C * D);

    // ---- Phase 1: normalize + scale ----
    #pragma unroll
    for (int rr = 0; rr < 4; rr++) {
        const int r = w * 4 + rr;
        const float bet = __ldg(beta + (size_t)nc * C + r);
        float4 q4 = *(const float4*)(q + base + r * D + lid * 4);
        float4 k4 = *(const float4*)(k + base + r * D + lid * 4);
        float4 v4 = *(const float4*)(v + base + r * D + lid * 4);
        float qs = q4.x*q4.x + q4.y*q4.y + q4.z*q4.z + q4.w*q4.w;
        float ks = k4.x*k4.x + k4.y*k4.y + k4.z*k4.z + k4.w*k4.w;
        #pragma unroll
        for (int o = 16; o > 0; o >>= 1) {
            qs += __shfl_xor_sync(0xffffffffu, qs, o);
            ks += __shfl_xor_sync(0xffffffffu, ks, o);
        }
        const float qr = rsqrtf(qs + 1e-6f);
        const float kr = rsqrtf(ks + 1e-6f);
        float4 qn = make_float4(q4.x*qr, q4.y*qr, q4.z*qr, q4.w*qr);
        float4 kn = make_float4(k4.x*kr, k4.y*kr, k4.z*kr, k4.w*kr);
        float4 kb = make_float4(kn.x*bet, kn.y*bet, kn.z*bet, kn.w*bet);
        float4 vb = make_float4(v4.x*bet, v4.y*bet, v4.z*bet, v4.w*bet);
        *(float4*)(sqn + r * RSTR + lid * 4) = qn;
        *(float4*)(skn + r * KSTR + ((lid ^ (r & 7)) << 2)) = kn;
        *(float4*)(skb + r * RSTR + lid * 4) = kb;
        *(float4*)(sv  + r * RSTR + lid * 4) = vb;
        *(float4*)(g_qn + base + r * D + lid * 4) = qn;
        *(float4*)(g_kn + base + r * D + lid * 4) = kn;
    }
    __syncthreads();

    // ---- Phase 2: A (strict-lower, negated) and attn (lower incl diag) ----
    {
        const int j  = lid;
        const int i0 = w * 4;
        const int jx = (j & 7);
        unsigned long long A0=0,A1=0,A2=0,A3=0,T0=0,T1=0,T2=0,T3=0;
        const float* kjp = skn + j * KSTR;
        const float* b0p = skb + (i0+0) * RSTR;
        const float* b1p = skb + (i0+1) * RSTR;
        const float* b2p = skb + (i0+2) * RSTR;
        const float* b3p = skb + (i0+3) * RSTR;
        const float* q0p = sqn + (i0+0) * RSTR;
        const float* q1p = sqn + (i0+1) * RSTR;
        const float* q2p = sqn + (i0+2) * RSTR;
        const float* q3p = sqn + (i0+3) * RSTR;
        #pragma unroll 4
        for (int d = 0; d < D; d += 4) {
            ulonglong2 kj = *(const ulonglong2*)(kjp + ((((d >> 2) ^ jx)) << 2));
            ulonglong2 b0 = *(const ulonglong2*)(b0p + d);
            ulonglong2 b1 = *(const ulonglong2*)(b1p + d);
            ulonglong2 b2 = *(const ulonglong2*)(b2p + d);
            ulonglong2 b3 = *(const ulonglong2*)(b3p + d);
            fma2(A0, b0.x, kj.x); fma2(A0, b0.y, kj.y);
            fma2(A1, b1.x, kj.x); fma2(A1, b1.y, kj.y);
            fma2(A2, b2.x, kj.x); fma2(A2, b2.y, kj.y);
            fma2(A3, b3.x, kj.x); fma2(A3, b3.y, kj.y);
            ulonglong2 c0 = *(const ulonglong2*)(q0p + d);
            ulonglong2 c1 = *(const ulonglong2*)(q1p + d);
            ulonglong2 c2 = *(const ulonglong2*)(q2p + d);
            ulonglong2 c3 = *(const ulonglong2*)(q3p + d);
            fma2(T0, c0.x, kj.x); fma2(T0, c0.y, kj.y);
            fma2(T1, c1.x, kj.x); fma2(T1, c1.y, kj.y);
            fma2(T2, c2.x, kj.x); fma2(T2, c2.y, kj.y);
            fma2(T3, c3.x, kj.x); fma2(T3, c3.y, kj.y);
        }
        const float a0 = hadd2(A0), a1 = hadd2(A1), a2 = hadd2(A2), a3 = hadd2(A3);
        const float t0 = hadd2(T0), t1 = hadd2(T1), t2 = hadd2(T2), t3 = hadd2(T3);
        float* ga = g_attn + (size_t)nc * (C * C);
        sA[(i0+0)*ASTR + j] = (j < i0+0) ? -a0 : 0.f;
        sA[(i0+1)*ASTR + j] = (j < i0+1) ? -a1 : 0.f;
        sA[(i0+2)*ASTR + j] = (j < i0+2) ? -a2 : 0.f;
        sA[(i0+3)*ASTR + j] = (j < i0+3) ? -a3 : 0.f;
        ga[(i0+0)*C + j] = (j <= i0+0) ? t0 : 0.f;
        ga[(i0+1)*C + j] = (j <= i0+1) ? t1 : 0.f;
        ga[(i0+2)*C + j] = (j <= i0+2) ? t2 : 0.f;
        ga[(i0+3)*C + j] = (j <= i0+3) ? t3 : 0.f;
    }
    __syncthreads();

    // ---- Phase 3a: two concurrent 16x16 substitutions (warps 0 & 1) ----
    // Warp b inverts diagonal block [16b,16b+16). Lane j (mod 16) owns column.
    if (w < 2) {
        const int b0 = w * 16;
        const int j  = lid & 15;              // lanes 16-31 shadow 0-15 (reads only)
        for (int i = 1; i < 16; i++) {
            float acc = 0.f;
            for (int kk = j + 1; kk < i; kk++)
                acc += sA[(b0+i)*ASTR + b0+kk] * sA[(b0+kk)*ASTR + b0+j];
            __syncwarp();
            if (lid < 16 && j < i) sA[(b0+i)*ASTR + b0+j] += acc;
            __syncwarp();
        }
        if (lid < 16) sA[(b0+j)*ASTR + b0+j] = 1.0f;   // unit diagonal
    }
    __syncthreads();

    // ---- Phase 3b: Schur combine  X21 = X22 * A21 * X11 ----
    // 256 threads: r = t>>4 (0..15), c = t&15.
    {
        const int r = t >> 4;
        const int cc = t & 15;
        // P = A21 * X11   (A21 = sA[16+r][0..15], untouched by 3a)
        float acc = 0.f;
        #pragma unroll 4
        for (int e = 0; e < 16; e++)
            acc += sA[(16+r)*ASTR + e] * sA[e*ASTR + cc];
        sP[r * 17 + cc] = acc;
        __syncthreads();
        // X21 = X22 * P   (X22 = sA[16+r][16..31] incl unit diag)
        float acc2 = 0.f;
        #pragma unroll 4
        for (int e = 0; e < 16; e++)
            acc2 += sA[(16+r)*ASTR + 16+e] * sP[e * 17 + cc];
        sA[(16+r)*ASTR + cc] = acc2;      // overwrite A21 (not read by this matmul)
    }
    __syncthreads();

    // ---- Phase 4: u = inv@v , w = inv@kb ----
    {
        const int i  = t >> 3;
        const int dl = (t & 7) * 4;
        #pragma unroll
        for (int db = 0; db < 4; db++) {
            const int d = db * 32 + dl;
            unsigned long long au01=0, au23=0, aw01=0, aw23=0;
            #pragma unroll 4
            for (int j0 = 0; j0 < C; j0 += 4) {
                float4 a4 = *(const float4*)(sA + i*ASTR + j0);
                #pragma unroll
                for (int jj = 0; jj < 4; jj++) {
                    const float av = (&a4.x)[jj];
                    unsigned long long a2 = pk2(av);
                    ulonglong2 v2 = *(const ulonglong2*)(sv  + (j0+jj)*RSTR + d);
                    ulonglong2 b2 = *(const ulonglong2*)(skb + (j0+jj)*RSTR + d);
                    fma2(au01, a2, v2.x); fma2(au23, a2, v2.y);
                    fma2(aw01, a2, b2.x); fma2(aw23, a2, b2.y);
                }
            }
            float2 l, h;
            l = up2(au01); h = up2(au23);
            *(float4*)(g_u + base + i*D + d) = make_float4(l.x, l.y, h.x, h.y);
            l = up2(aw01); h = up2(aw23);
            *(float4*)(g_w + base + i*D + d) = make_float4(l.x, l.y, h.x, h.y);
        }
    }
}

// ---------------------------------------------------------------------------
// Scan kernel: 256 threads. Phase 2: 4-row register tiling + d-quarters, ALL
// quarters store partials, combine distributed over all 256 threads.
// ---------------------------------------------------------------------------
#define SBUF (3 * C * RSTR + 2 * C * ASTR)   // q,k,w tiles + u0 + attn per buffer
#define PMAT (C * ASTR)                       // one 32x32 partial matrix

__device__ __forceinline__ void prefetch_chunk(
    uint32_t smb, int ci, int w, int lid, int c, int v4, int v0,
    const float* gq, const float* gk, const float* gw,
    const float* gu, const float* ga)
{
    const size_t cb = (size_t)ci * (C * D);
    const uint32_t OK  = (uint32_t)(C * RSTR) * 4u;
    const uint32_t OW  = 2u * OK;
    const uint32_t OU0 = 3u * OK;
    const uint32_t OAT = OU0 + (uint32_t)(C * ASTR) * 4u;
    #pragma unroll
    for (int rr = 0; rr < 4; rr++) {
        const int r = w * 4 + rr;
        const uint32_t off = (uint32_t)(r * RSTR + lid * 4) * 4u;
        cpa16(smb +      off, gq + cb + r * D + lid * 4);
        cpa16(smb + OK + off, gk + cb + r * D + lid * 4);
        cpa16(smb + OW + off, gw + cb + r * D + lid * 4);
    }
    cpa16(smb + OU0 + (uint32_t)(c * ASTR + v4) * 4u, gu + cb + c * D + v0 + v4);
    cpa16(smb + OAT + (uint32_t)(c * ASTR + v4) * 4u,
          ga + (size_t)ci * (C * C) + c * C + v4);
    asm volatile("cp.async.commit_group;");
}

__global__ void __launch_bounds__(256, 1) scan_kernel(float* __restrict__ out)
{
    extern __shared__ float s[];
    float* sS  = s;                         // 128 x VSLICE
    float* sb0 = sS + D * VSLICE;
    float* sb1 = sb0 + SBUF;
    float* sui = sb1 + SBUF;                // 32 x ASTR
    float* sPQ = sui + C * ASTR;            // 32 x ASTR (final q@S)
    float* sPP = sPQ + C * ASTR;            // 8 x PMAT partial matrices (4 U, 4 Q)

    const int bh  = blockIdx.y;
    const int v0  = blockIdx.x * VSLICE;
    const int t   = threadIdx.x;
    const int w   = t >> 5;
    const int lid = t & 31;
    // phase-2 mapping: v4-group x 4-row block x d-quarter
    const int v4  = (t & 7) * 4;
    const int r0  = ((t >> 3) & 7) * 4;     // rows r0..r0+3
    const int dq  = t >> 6;                 // d quarter 0..3
    // phase-3/4 and combine mapping
    const int c   = t >> 3;

    // zero S
    #pragma unroll
    for (int rr = 0; rr < 4; rr++)
        *(float4*)(sS + (rr * 256 + t) * 4) = make_float4(0.f, 0.f, 0.f, 0.f);

    const uint32_t smb0 = (uint32_t)__cvta_generic_to_shared(sb0);
    const uint32_t smb1 = (uint32_t)__cvta_generic_to_shared(sb1);

    const size_t bhb = (size_t)bh * LSEQ * D;
    const float* gq = g_qn + bhb;
    const float* gk = g_kn + bhb;
    const float* gw = g_w  + bhb;
    const float* gu = g_u  + bhb;
    const float* ga = g_attn + (size_t)bh * NCHUNK * (C * C);

    prefetch_chunk(smb0, 0, w, lid, c, v4, v0, gq, gk, gw, gu, ga);

    for (int ci = 0; ci < NCHUNK; ci++) {
        float* B = (ci & 1) ? sb1 : sb0;
        const uint32_t smn = (ci & 1) ? smb0 : smb1;
        const float* sq  = B;
        const float* sk  = B + C * RSTR;
        const float* sw  = B + 2 * C * RSTR;
        const float* su0 = B + 3 * C * RSTR;
        const float* sat = su0 + C * ASTR;

        asm volatile("cp.async.wait_group 0;");
        __syncthreads();                    // tiles ready + prev S update done

        const int cn = (ci + 1 < NCHUNK) ? ci + 1 : ci;
        prefetch_chunk(smn, cn, w, lid, c, v4, v0, gq, gk, gw, gu, ga);

        // ---- phase 2: quarter-d GEMV, 4 rows/thread; ALL quarters store ----
        {
            unsigned long long aU[4][2], aQ[4][2];
            #pragma unroll
            for (int r = 0; r < 4; r++) {
                aU[r][0]=0; aU[r][1]=0; aQ[r][0]=0; aQ[r][1]=0;
            }
            const int dbeg = dq * 32;
            const float* wp = sw + dbeg;
            const float* qp = sq + dbeg;
            const float* Sp = sS + dbeg * VSLICE + v4;
            #pragma unroll 2
            for (int dg = 0; dg < 32; dg += 4) {
                float4 wv[4], qv[4];
                #pragma unroll
                for (int r = 0; r < 4; r++) {
                    wv[r] = *(const float4*)(wp + (r0 + r) * RSTR + dg);
                    qv[r] = *(const float4*)(qp + (r0 + r) * RSTR + dg);
                }
                #pragma unroll
                for (int i = 0; i < 4; i++) {
                    ulonglong2 S2 = *(const ulonglong2*)(Sp + (dg + i) * VSLICE);
                    #pragma unroll
                    for (int r = 0; r < 4; r++) {
                        unsigned long long w2 = pk2((&wv[r].x)[i]);
                        unsigned long long q2 = pk2((&qv[r].x)[i]);
                        fma2(aU[r][0], w2, S2.x); fma2(aU[r][1], w2, S2.y);
                        fma2(aQ[r][0], q2, S2.x); fma2(aQ[r][1], q2, S2.y);
                    }
                }
            }
            float* PU = sPP + dq * PMAT;
            float* PQ = sPP + (4 + dq) * PMAT;
            #pragma unroll
            for (int r = 0; r < 4; r++) {
                float2 l, h;
                l = up2(aU[r][0]); h = up2(aU[r][1]);
                *(float4*)(PU + (r0 + r) * ASTR + v4) = make_float4(l.x, l.y, h.x, h.y);
                l = up2(aQ[r][0]); h = up2(aQ[r][1]);
                *(float4*)(PQ + (r0 + r) * ASTR + v4) = make_float4(l.x, l.y, h.x, h.y);
            }
        }
        __syncthreads();

        // ---- combine (ALL 256 threads): one (c, v4) each ----
        {
            float4 u0 = *(const float4*)(su0 + c * ASTR + v4);
            float4 aU = make_float4(0.f,0.f,0.f,0.f);
            float4 aQ = make_float4(0.f,0.f,0.f,0.f);
            #pragma unroll
            for (int p = 0; p < 4; p++) {
                float4 pu = *(const float4*)(sPP + p * PMAT + c * ASTR + v4);
                float4 pq = *(const float4*)(sPP + (4+p) * PMAT + c * ASTR + v4);
                aU.x += pu.x; aU.y += pu.y; aU.z += pu.z; aU.w += pu.w;
                aQ.x += pq.x; aQ.y += pq.y; aQ.z += pq.z; aQ.w += pq.w;
            }
            *(float4*)(sui + c * ASTR + v4) = make_float4(
                u0.x - aU.x, u0.y - aU.y, u0.z - aU.z, u0.w - aU.w);
            *(float4*)(sPQ + c * ASTR + v4) = aQ;
        }
        __syncthreads();

        // ---- phase 3: out = q@S + attn @ u_i (all 256 threads) ----
        {
            float4 a0 = *(const float4*)(sPQ + c * ASTR + v4);
            unsigned long long o01 = pkf(a0.x, a0.y);
            unsigned long long o23 = pkf(a0.z, a0.w);
            #pragma unroll 8
            for (int e = 0; e < C; e++) {
                unsigned long long a2 = pk2(sat[c * ASTR + e]);
                ulonglong2 u2 = *(const ulonglong2*)(sui + e * ASTR + v4);
                fma2(o01, a2, u2.x); fma2(o23, a2, u2.y);
            }
            float2 l = up2(o01), h = up2(o23);
            *(float4*)(out + bhb + (size_t)ci * (C * D) + c * D + v0 + v4) =
                make_float4(l.x, l.y, h.x, h.y);
        }

        // ---- phase 4: S[d,v] += sum_e k[e,d] * u_i[e,v] ----
        {
            unsigned long long A0=0,A1=0,A2=0,A3=0,A4=0,A5=0,A6=0,A7=0;
            #pragma unroll 4
            for (int e = 0; e < C; e++) {
                ulonglong2 u2 = *(const ulonglong2*)(sui + e * ASTR + v4);
                unsigned long long k0 = pk2(sk[e * RSTR + c]);
                unsigned long long k1 = pk2(sk[e * RSTR + c + 32]);
                unsigned long long k2 = pk2(sk[e * RSTR + c + 64]);
                unsigned long long k3 = pk2(sk[e * RSTR + c + 96]);
                fma2(A0, k0, u2.x); fma2(A1, k0, u2.y);
                fma2(A2, k1, u2.x); fma2(A3, k1, u2.y);
                fma2(A4, k2, u2.x); fma2(A5, k2, u2.y);
                fma2(A6, k3, u2.x); fma2(A7, k3, u2.y);
            }
            float2 l, h;
            float4* p0 = (float4*)(sS + (c      ) * VSLICE + v4);
            float4* p1 = (float4*)(sS + (c +  32) * VSLICE + v4);
            float4* p2 = (float4*)(sS + (c +  64) * VSLICE + v4);
            float4* p3 = (float4*)(sS + (c +  96) * VSLICE + v4);
            float4 t0 = *p0, t1 = *p1, t2 = *p2, t3 = *p3;
            l = up2(A0); h = up2(A1);
            t0.x += l.x; t0.y += l.y; t0.z += h.x; t0.w += h.y;
            l = up2(A2); h = up2(A3);
            t1.x += l.x; t1.y += l.y; t1.z += h.x; t1.w += h.y;
            l = up2(A4); h = up2(A5);
            t2.x += l.x; t2.y += l.y; t2.z += h.x; t2.w += h.y;
            l = up2(A6); h = up2(A7);
            t3.x += l.x; t3.y += l.y; t3.z += h.x; t3.w += h.y;
            *p0 = t0; *p1 = t1; *p2 = t2; *p3 = t3;
        }
    }
}

// ---------------------------------------------------------------------------
extern "C" void kernel_launch(void* const* d_in, const int* in_sizes, int n_in,
                              void* d_out, int out_size)
{
    const float* q    = (const float*)d_in[0];
    const float* k    = (const float*)d_in[1];
    const float* v    = (const float*)d_in[2];
    const float* beta = (const float*)d_in[3];
    float* out = (float*)d_out;

    const size_t smemA = (size_t)(3 * C * RSTR + C * KSTR + C * ASTR + 16 * 17)
                         * sizeof(float);
    const size_t smemB = (size_t)(D * VSLICE + 2 * SBUF + 2 * C * ASTR + 8 * PMAT)
                         * sizeof(float);

    cudaFuncSetAttribute(prep_kernel, cudaFuncAttributeMaxDynamicSharedMemorySize,
                         (int)smemA);
    cudaFuncSetAttribute(scan_kernel, cudaFuncAttributeMaxDynamicSharedMemorySize,
                         (int)smemB);

    prep_kernel<<<NC_TOTAL, 256, smemA>>>(q, k, v, beta);
    scan_kernel<<<dim3(NSPLIT, BH), 256, smemB>>>(out);
}